// round 11
// baseline (speedup 1.0000x reference)
#include <cuda_runtime.h>
#include <cuda_bf16.h>

// Problem constants (fixed shapes from reference)
#define NB     64
#define CC     256
#define EMB    16
#define HW     3136                 // 56*56
#define IDX    16                   // ceil(256^(0.5))
#define SCALEF (256.0f / 240.0f)    // c / (c - INDEX)

#define TOTAL4   ((unsigned)NB * CC * HW / 4)  // 12,845,056 float4
#define SLAB4    (HW / 4)                      // 784 float4 per (n,c) slab
#define BLK_F4   2048u                         // float4 per block (256 thr * 8)
#define BLKS_PER_N 98u                         // 2048*98 == 256*784 exactly
#define NBLOCKS  (TOTAL4 / BLK_F4)             // 6272 == 98*64

// Cross-block state (zero-initialized in cubin; reset to zero by the last
// finisher each launch, so every launch is state-identical).
__device__ float    g_mult[NB * CC];   // per-(n,c) multiplier row
__device__ unsigned g_flag[NB];        // per-sample "mask ready" flag
__device__ unsigned g_done;            // finished-block counter

// ---------------------------------------------------------------------------
// Single fused kernel. Block bid streams tile bid (2048 contiguous float4,
// always inside sample n = bid/98). The FIRST block of each sample's group
// (bid % 98 == 0) is the producer: it computes the channel mask, publishes it
// (threadfence + flag), and keeps its own copy in smem. The other 97 blocks
// spin (thread 0 only, ~2us) on their sample's flag, then pull the mask row
// into smem. Producer bid < consumer bid, and CTAs dispatch in nondecreasing
// bid order, so the producer is always scheduled no later than its waiters.
//
// Stream phase: batch-8 LDG.128.CS -> scale (mask via LDS) -> STG.128.CS.
// __launch_bounds__(256,4) keeps the 64-reg budget that R8 showed is needed
// for genuine 8-deep MLP. Branch-free: x finite => x*0 == 0 exactly.
// ---------------------------------------------------------------------------
__global__ void __launch_bounds__(256, 4)
drop_fused_kernel(const float4* __restrict__ x,
                  const float*  __restrict__ embeds,
                  const float*  __restrict__ table,
                  float4* __restrict__ out) {
    __shared__ float s_emb[EMB];
    __shared__ float s_act[CC];
    __shared__ float s_mult[CC];
    __shared__ float s_thr;

    const unsigned t   = threadIdx.x;
    const unsigned bid = blockIdx.x;
    const unsigned n   = bid / BLKS_PER_N;

    if (bid % BLKS_PER_N == 0u) {
        // ---- producer: compute this sample's mask ----------------------
        if (t < EMB) s_emb[t] = embeds[n * EMB + t];
        __syncthreads();

        float a = 0.0f;
#pragma unroll
        for (int e = 0; e < EMB; e++)
            a = fmaf(s_emb[e], table[e * CC + t], a);   // coalesced across t
        s_act[t] = a;
        __syncthreads();

        // Rank of this thread's value among the 256 row values.
        const float4* act4 = (const float4*)s_act;
        int less = 0, leq = 0;
#pragma unroll 8
        for (int j = 0; j < CC / 4; j++) {
            const float4 w = act4[j];
            less += (w.x <  a) + (w.y <  a) + (w.z <  a) + (w.w <  a);
            leq  += (w.x <= a) + (w.y <= a) + (w.z <= a) + (w.w <= a);
        }
        // Sorted-index-IDX element: #{< v} <= IDX and #{<= v} > IDX (tie-safe).
        if (less <= IDX && leq > IDX) s_thr = a;
        __syncthreads();

        const float mval = (s_thr <= a) ? SCALEF : 0.0f;
        s_mult[t] = mval;
        g_mult[n * CC + t] = mval;       // publish for the other 97 blocks
        __threadfence();                 // order row stores before flag
        __syncthreads();
        if (t == 0) atomicExch(&g_flag[n], 1u);
    } else {
        // ---- consumer: wait for this sample's mask ---------------------
        if (t == 0) {
            while (atomicAdd(&g_flag[n], 0u) == 0u) __nanosleep(64);
        }
        __syncthreads();
        __threadfence();                 // acquire: row stores now visible
        s_mult[t] = g_mult[n * CC + t];
        __syncthreads();
    }

    // ---- stream phase: 8 float4 per thread, batched loads --------------
    const unsigned base = bid * BLK_F4 + t;

    float m[8];
#pragma unroll
    for (int k = 0; k < 8; k++) {
        const unsigned i = base + (unsigned)k * 256u;
        m[k] = s_mult[(i / SLAB4) & (CC - 1)];           // LDS, channel in sample
    }

    float4 v[8];
#pragma unroll
    for (int k = 0; k < 8; k++)
        v[k] = __ldcs(&x[base + (unsigned)k * 256u]);    // 8 LDG.128.CS batched

#pragma unroll
    for (int k = 0; k < 8; k++) {
        v[k].x *= m[k]; v[k].y *= m[k]; v[k].z *= m[k]; v[k].w *= m[k];
        __stcs(&out[base + (unsigned)k * 256u], v[k]);
    }

    // ---- reset protocol: last finisher zeroes the flags ----------------
    __syncthreads();
    if (t == 0) {
        const unsigned d = atomicAdd(&g_done, 1u);
        if (d == NBLOCKS - 1u) {
            // Everyone has passed their spin and finished; safe to reset.
#pragma unroll
            for (int i = 0; i < NB; i++) g_flag[i] = 0u;
            g_done = 0u;
            __threadfence();
        }
    }
}

extern "C" void kernel_launch(void* const* d_in, const int* in_sizes, int n_in,
                              void* d_out, int out_size) {
    const float* x      = (const float*)d_in[0];   // [64,256,56,56]
    const float* embeds = (const float*)d_in[1];   // [64,16]
    const float* table  = (const float*)d_in[2];   // [16,256]
    float* out = (float*)d_out;

    drop_fused_kernel<<<NBLOCKS, 256>>>((const float4*)x, embeds, table,
                                        (float4*)out);
}